// round 6
// baseline (speedup 1.0000x reference)
#include <cuda_runtime.h>
#include <cuda_fp16.h>
#include <cstdint>

#define HW    65536
#define CCH   64
#define NPIX  (16 * HW)            // 1,048,576 pixels
#define NTOT  (16 * CCH * HW)      // 67,108,864 elements

// ---------------- device scratch (allocation-free) ---------------------------
__device__ short    g_bufA[NTOT];     // int16 scaled-acc intermediates
__device__ short    g_bufB[NTOT];
__device__ __half   g_bufC[NTOT];     // fp16 shadow of x
__device__ unsigned g_amax[4];        // abs-max bits of: x, y1, y3, y4 (idempotent across runs)
__device__ float    g_wscale[4];      // scales of: w_p1, w_f1, w_p2, w_f2
__device__ int      g_qwp[2][1024];   // packed int8 pointwise weights [co][ci/4]
__device__ int      g_qwfi[2][192];   // packed int8 dw weight rows [c][3] = (w0,w1,w2,0)

// ---------------- init: weight prep (blocks 0-3) + absmax/x16 (rest) ---------
__global__ void __launch_bounds__(256) k_init(const float4* __restrict__ x, int nvec,
                                              const float* __restrict__ wp1,
                                              const float* __restrict__ wf1,
                                              const float* __restrict__ wp2,
                                              const float* __restrict__ wf2)
{
    if (blockIdx.x < 4) {
        int b = blockIdx.x;   // 0:wp1 1:wf1 2:wp2 3:wf2
        const float* w = (b == 0) ? wp1 : (b == 1) ? wf1 : (b == 2) ? wp2 : wf2;
        int n = (b & 1) ? 576 : 4096;

        __shared__ float red[256];
        float m = 0.f;
        for (int i = threadIdx.x; i < n; i += 256) m = fmaxf(m, fabsf(w[i]));
        red[threadIdx.x] = m;
        __syncthreads();
        for (int s = 128; s > 0; s >>= 1) {
            if (threadIdx.x < s) red[threadIdx.x] = fmaxf(red[threadIdx.x], red[threadIdx.x + s]);
            __syncthreads();
        }
        __shared__ float s_scale;
        if (threadIdx.x == 0) {
            float sc = red[0] / 7.0f + 1e-12f;
            g_wscale[b] = sc;
            s_scale = sc;
        }
        __syncthreads();
        float sc = s_scale;

        if (b & 1) {
            for (int i = threadIdx.x; i < 192; i += 256) {
                const float* wr = w + (i / 3) * 9 + (i % 3) * 3;
                int q0 = (int)fminf(fmaxf(rintf(wr[0] / sc), -7.f), 7.f);
                int q1 = (int)fminf(fmaxf(rintf(wr[1] / sc), -7.f), 7.f);
                int q2 = (int)fminf(fmaxf(rintf(wr[2] / sc), -7.f), 7.f);
                g_qwfi[b >> 1][i] = (q0 & 0xFF) | ((q1 & 0xFF) << 8) | ((q2 & 0xFF) << 16);
            }
        } else {
            for (int i = threadIdx.x; i < 1024; i += 256) {
                int word = 0;
                #pragma unroll
                for (int j = 0; j < 4; j++) {
                    float q = fminf(fmaxf(rintf(w[i * 4 + j] / sc), -7.f), 7.f);
                    word |= ((int)q & 0xFF) << (8 * j);
                }
                g_qwp[b >> 1][i] = word;
            }
        }
        return;
    }

    // ---- absmax(x) + fp16 shadow copy ----
    uint2* __restrict__ c16 = reinterpret_cast<uint2*>(g_bufC);
    int stride = (gridDim.x - 4) * 256;
    float m = 0.f;
    for (int i = (blockIdx.x - 4) * 256 + threadIdx.x; i < nvec; i += stride) {
        float4 v = __ldcs(&x[i]);
        __half2 h01 = __floats2half2_rn(v.x, v.y);
        __half2 h23 = __floats2half2_rn(v.z, v.w);
        uint2 st;
        st.x = *reinterpret_cast<unsigned*>(&h01);
        st.y = *reinterpret_cast<unsigned*>(&h23);
        c16[i] = st;
        m = fmaxf(m, fmaxf(fmaxf(fabsf(v.x), fabsf(v.y)), fmaxf(fabsf(v.z), fabsf(v.w))));
    }
    #pragma unroll
    for (int off = 16; off; off >>= 1) m = fmaxf(m, __shfl_xor_sync(0xFFFFFFFFu, m, off));
    __shared__ float wm[8];
    int lane = threadIdx.x & 31, wid = threadIdx.x >> 5;
    if (lane == 0) wm[wid] = m;
    __syncthreads();
    if (threadIdx.x == 0) {
        float mm = wm[0];
        #pragma unroll
        for (int i = 1; i < 8; i++) mm = fmaxf(mm, wm[i]);
        atomicMax(&g_amax[0], __float_as_uint(mm));
    }
}

// ---------------- pw0: x16 -> int16 half-accs, amax[0] -> amax[1] ------------
__global__ void __launch_bounds__(128) k_pw0()
{
    __shared__ __align__(16) int ws[1024];
    for (int i = threadIdx.x; i < 1024; i += 128) ws[i] = g_qwp[0][i];
    __syncthreads();

    float s_in = __uint_as_float(g_amax[0]) * (1.0f / 127.0f) + 1e-12f;
    float inv  = 1.0f / s_in;
    float osc  = s_in * g_wscale[0];

    unsigned p  = (blockIdx.x * 128u + threadIdx.x) * 4u;
    unsigned base = (p >> 16) * (CCH * HW) + (p & 0xFFFFu);

    int xq0[16], xq1[16], xq2[16], xq3[16];
    #pragma unroll
    for (int k = 0; k < 16; k++) {
        int w0 = 0, w1 = 0, w2 = 0, w3 = 0;
        #pragma unroll
        for (int j = 0; j < 4; j++) {
            uint2 raw = *reinterpret_cast<const uint2*>(g_bufC + base + (unsigned)(4 * k + j) * HW);
            float2 f01 = __half22float2(*reinterpret_cast<__half2*>(&raw.x));
            float2 f23 = __half22float2(*reinterpret_cast<__half2*>(&raw.y));
            w0 |= (__float2int_rn(f01.x * inv) & 0xFF) << (8 * j);
            w1 |= (__float2int_rn(f01.y * inv) & 0xFF) << (8 * j);
            w2 |= (__float2int_rn(f23.x * inv) & 0xFF) << (8 * j);
            w3 |= (__float2int_rn(f23.y * inv) & 0xFF) << (8 * j);
        }
        xq0[k] = w0; xq1[k] = w1; xq2[k] = w2; xq3[k] = w3;
    }

    int maxi = 0;
    #pragma unroll 2
    for (int co = 0; co < 64; co++) {
        int a0 = 0, a1 = 0, a2 = 0, a3 = 0;
        #pragma unroll
        for (int k4 = 0; k4 < 4; k4++) {
            int4 w4 = *reinterpret_cast<const int4*>(&ws[co * 16 + k4 * 4]);
            a0 = __dp4a(w4.x, xq0[4 * k4 + 0], a0);
            a0 = __dp4a(w4.y, xq0[4 * k4 + 1], a0);
            a0 = __dp4a(w4.z, xq0[4 * k4 + 2], a0);
            a0 = __dp4a(w4.w, xq0[4 * k4 + 3], a0);
            a1 = __dp4a(w4.x, xq1[4 * k4 + 0], a1);
            a1 = __dp4a(w4.y, xq1[4 * k4 + 1], a1);
            a1 = __dp4a(w4.z, xq1[4 * k4 + 2], a1);
            a1 = __dp4a(w4.w, xq1[4 * k4 + 3], a1);
            a2 = __dp4a(w4.x, xq2[4 * k4 + 0], a2);
            a2 = __dp4a(w4.y, xq2[4 * k4 + 1], a2);
            a2 = __dp4a(w4.z, xq2[4 * k4 + 2], a2);
            a2 = __dp4a(w4.w, xq2[4 * k4 + 3], a2);
            a3 = __dp4a(w4.x, xq3[4 * k4 + 0], a3);
            a3 = __dp4a(w4.y, xq3[4 * k4 + 1], a3);
            a3 = __dp4a(w4.z, xq3[4 * k4 + 2], a3);
            a3 = __dp4a(w4.w, xq3[4 * k4 + 3], a3);
        }
        maxi = max(maxi, max(max(abs(a0), abs(a1)), max(abs(a2), abs(a3))));
        int s0 = (a0 + 1) >> 1, s1 = (a1 + 1) >> 1;
        int s2 = (a2 + 1) >> 1, s3 = (a3 + 1) >> 1;
        uint2 st;
        st.x = (s0 & 0xFFFF) | (s1 << 16);
        st.y = (s2 & 0xFFFF) | (s3 << 16);
        *reinterpret_cast<uint2*>(g_bufA + base + (unsigned)co * HW) = st;
    }

    float lmax = (float)maxi * osc;
    #pragma unroll
    for (int off = 16; off; off >>= 1) lmax = fmaxf(lmax, __shfl_xor_sync(0xFFFFFFFFu, lmax, off));
    __shared__ float wm[4];
    int lane = threadIdx.x & 31, wid = threadIdx.x >> 5;
    if (lane == 0) wm[wid] = lmax;
    __syncthreads();
    if (threadIdx.x == 0)
        atomicMax(&g_amax[1], __float_as_uint(fmaxf(fmaxf(wm[0], wm[1]), fmaxf(wm[2], wm[3]))));
}

// ---------------- pw1: dw0 raw accs (int16) -> int16 half-accs ---------------
// input value = s * osc_dw0 (exact); PReLU folded into per-channel kp/kn.
__global__ void __launch_bounds__(128) k_pw1(const float* __restrict__ alpha1)
{
    __shared__ __align__(16) int ws[1024];
    __shared__ float kns[64];

    float s_dw0  = __uint_as_float(g_amax[1]) * (1.0f / 127.0f) + 1e-12f;
    float oscdw0 = s_dw0 * g_wscale[1];                 // dw0 int acc -> fp value
    float s_in1  = __uint_as_float(g_amax[2]) * (1.0f / 127.0f) + 1e-12f;
    float kp     = oscdw0 / s_in1;
    float osc    = s_in1 * g_wscale[2];                 // our acc -> fp value

    for (int i = threadIdx.x; i < 1024; i += 128) ws[i] = g_qwp[1][i];
    if (threadIdx.x < 64) kns[threadIdx.x] = alpha1[threadIdx.x] * kp;
    __syncthreads();

    unsigned p  = (blockIdx.x * 128u + threadIdx.x) * 4u;
    unsigned base = (p >> 16) * (CCH * HW) + (p & 0xFFFFu);

    int xq0[16], xq1[16], xq2[16], xq3[16];
    #pragma unroll
    for (int k = 0; k < 16; k++) {
        int w0 = 0, w1 = 0, w2 = 0, w3 = 0;
        #pragma unroll
        for (int j = 0; j < 4; j++) {
            unsigned ci = 4 * k + j;
            float kn = kns[ci];
            uint2 raw = *reinterpret_cast<const uint2*>(g_bufB + base + ci * HW);
            int t0 = (short)(raw.x), t1 = (short)(raw.x >> 16);
            int t2 = (short)(raw.y), t3 = (short)(raw.y >> 16);
            w0 |= (__float2int_rn((float)t0 * (t0 > 0 ? kp : kn)) & 0xFF) << (8 * j);
            w1 |= (__float2int_rn((float)t1 * (t1 > 0 ? kp : kn)) & 0xFF) << (8 * j);
            w2 |= (__float2int_rn((float)t2 * (t2 > 0 ? kp : kn)) & 0xFF) << (8 * j);
            w3 |= (__float2int_rn((float)t3 * (t3 > 0 ? kp : kn)) & 0xFF) << (8 * j);
        }
        xq0[k] = w0; xq1[k] = w1; xq2[k] = w2; xq3[k] = w3;
    }

    int maxi = 0;
    #pragma unroll 2
    for (int co = 0; co < 64; co++) {
        int a0 = 0, a1 = 0, a2 = 0, a3 = 0;
        #pragma unroll
        for (int k4 = 0; k4 < 4; k4++) {
            int4 w4 = *reinterpret_cast<const int4*>(&ws[co * 16 + k4 * 4]);
            a0 = __dp4a(w4.x, xq0[4 * k4 + 0], a0);
            a0 = __dp4a(w4.y, xq0[4 * k4 + 1], a0);
            a0 = __dp4a(w4.z, xq0[4 * k4 + 2], a0);
            a0 = __dp4a(w4.w, xq0[4 * k4 + 3], a0);
            a1 = __dp4a(w4.x, xq1[4 * k4 + 0], a1);
            a1 = __dp4a(w4.y, xq1[4 * k4 + 1], a1);
            a1 = __dp4a(w4.z, xq1[4 * k4 + 2], a1);
            a1 = __dp4a(w4.w, xq1[4 * k4 + 3], a1);
            a2 = __dp4a(w4.x, xq2[4 * k4 + 0], a2);
            a2 = __dp4a(w4.y, xq2[4 * k4 + 1], a2);
            a2 = __dp4a(w4.z, xq2[4 * k4 + 2], a2);
            a2 = __dp4a(w4.w, xq2[4 * k4 + 3], a2);
            a3 = __dp4a(w4.x, xq3[4 * k4 + 0], a3);
            a3 = __dp4a(w4.y, xq3[4 * k4 + 1], a3);
            a3 = __dp4a(w4.z, xq3[4 * k4 + 2], a3);
            a3 = __dp4a(w4.w, xq3[4 * k4 + 3], a3);
        }
        maxi = max(maxi, max(max(abs(a0), abs(a1)), max(abs(a2), abs(a3))));
        int s0 = (a0 + 1) >> 1, s1 = (a1 + 1) >> 1;
        int s2 = (a2 + 1) >> 1, s3 = (a3 + 1) >> 1;
        uint2 st;
        st.x = (s0 & 0xFFFF) | (s1 << 16);
        st.y = (s2 & 0xFFFF) | (s3 << 16);
        *reinterpret_cast<uint2*>(g_bufA + base + (unsigned)co * HW) = st;
    }

    float lmax = (float)maxi * osc;
    #pragma unroll
    for (int off = 16; off; off >>= 1) lmax = fmaxf(lmax, __shfl_xor_sync(0xFFFFFFFFu, lmax, off));
    __shared__ float wm[4];
    int lane = threadIdx.x & 31, wid = threadIdx.x >> 5;
    if (lane == 0) wm[wid] = lmax;
    __syncthreads();
    if (threadIdx.x == 0)
        atomicMax(&g_amax[3], __float_as_uint(fmaxf(fmaxf(wm[0], wm[1]), fmaxf(wm[2], wm[3]))));
}

// ---------------- depthwise 3x3 (exact int8 dp4a) + PReLU (+residual) --------
// WHICH 0: bufA(s16 = pw0 acc/2) -> bufB(s16 = raw dw acc), fused amax[2]
// WHICH 1: bufA(s16 = pw1 acc/2) -> dout(fp32) + residual bufC(half x)
template<int WHICH>
__global__ void __launch_bounds__(128) k_dw(float* __restrict__ dout,
                                            const float* __restrict__ alpha)
{
    int bc    = blockIdx.x >> 3;     // 0..1023
    int strip = blockIdx.x & 7;
    int c     = bc & 63;
    int warp  = threadIdx.x >> 5;
    int lane  = threadIdx.x & 31;
    int rbase = strip * 32 + warp * 8;
    int col0  = lane * 8;

    // input: s16 with value = 2*s*osc_pw ; quantize with fused kq
    float s_pw  = __uint_as_float(g_amax[WHICH == 0 ? 0 : 2]) * (1.0f / 127.0f) + 1e-12f;
    float oscpw = s_pw * g_wscale[WHICH == 0 ? 0 : 2];
    float s_in  = __uint_as_float(g_amax[WHICH == 0 ? 1 : 3]) * (1.0f / 127.0f) + 1e-12f;
    float kq    = 2.0f * oscpw / s_in;
    float osc   = s_in * g_wscale[WHICH == 0 ? 1 : 3];   // dw int acc -> fp value

    int wr0 = g_qwfi[WHICH][c * 3 + 0];
    int wr1 = g_qwfi[WHICH][c * 3 + 1];
    int wr2 = g_qwfi[WHICH][c * 3 + 2];
    float a = alpha[c];

    const short* in = g_bufA + (unsigned)bc * HW;
    int accT[8], accM[8];
    #pragma unroll
    for (int j = 0; j < 8; j++) { accT[j] = 0; accM[j] = 0; }
    float lmax = 0.f;

    uint4 nxt;
    {
        int rr = rbase - 1;
        nxt = (rr >= 0) ? *reinterpret_cast<const uint4*>(in + rr * 256 + col0)
                        : make_uint4(0, 0, 0, 0);
    }

    #pragma unroll
    for (int k = 0; k < 10; k++) {
        uint4 raw = nxt;
        int rr = rbase - 1 + k;
        bool valid = (rr >= 0 && rr < 256);
        if (k < 9) {                       // prefetch next row
            int rn = rbase + k;
            nxt = (rn < 256) ? *reinterpret_cast<const uint4*>(in + rn * 256 + col0)
                             : make_uint4(0, 0, 0, 0);
        }

        unsigned wA = 0, wB = 0;
        if (valid) {
            int q0 = __float2int_rn((float)(short)(raw.x)       * kq);
            int q1 = __float2int_rn((float)(short)(raw.x >> 16) * kq);
            int q2 = __float2int_rn((float)(short)(raw.y)       * kq);
            int q3 = __float2int_rn((float)(short)(raw.y >> 16) * kq);
            int q4 = __float2int_rn((float)(short)(raw.z)       * kq);
            int q5 = __float2int_rn((float)(short)(raw.z >> 16) * kq);
            int q6 = __float2int_rn((float)(short)(raw.w)       * kq);
            int q7 = __float2int_rn((float)(short)(raw.w >> 16) * kq);
            wA = __byte_perm(__byte_perm(q0, q1, 0x0040),
                             __byte_perm(q2, q3, 0x0040), 0x5410);
            wB = __byte_perm(__byte_perm(q4, q5, 0x0040),
                             __byte_perm(q6, q7, 0x0040), 0x5410);
        }
        unsigned wPrev = __shfl_up_sync(0xFFFFFFFFu, wB, 1);
        unsigned wNext = __shfl_down_sync(0xFFFFFFFFu, wA, 1);
        if (lane == 0)  wPrev = 0;
        if (lane == 31) wNext = 0;

        unsigned win[8];
        win[0] = __byte_perm(wPrev, wA, 0x0543);
        win[1] = wA;
        win[2] = __byte_perm(wA, wB, 0x4321);
        win[3] = __byte_perm(wA, wB, 0x5432);
        win[4] = __byte_perm(wA, wB, 0x6543);
        win[5] = wB;
        win[6] = __byte_perm(wB, wNext, 0x4321);
        win[7] = __byte_perm(wB, wNext, 0x5432);

        if (k >= 2) {
            int ro = rbase + k - 2;
            unsigned off = (unsigned)bc * HW + (unsigned)(ro * 256 + col0);
            int acc[8];
            float y[8];
            #pragma unroll
            for (int j = 0; j < 8; j++) {
                acc[j] = __dp4a((int)win[j], wr2, accM[j]);
                float v = (float)acc[j] * osc;
                y[j] = (v > 0.f) ? v : a * v;
            }
            if (WHICH == 0) {
                #pragma unroll
                for (int j = 0; j < 8; j++) lmax = fmaxf(lmax, fabsf(y[j]));
                uint4 st;   // raw accs as shorts (exact, |acc| <= 8001)
                st.x = (acc[0] & 0xFFFF) | (acc[1] << 16);
                st.y = (acc[2] & 0xFFFF) | (acc[3] << 16);
                st.z = (acc[4] & 0xFFFF) | (acc[5] << 16);
                st.w = (acc[6] & 0xFFFF) | (acc[7] << 16);
                *reinterpret_cast<uint4*>(g_bufB + off) = st;
            } else {
                uint4 rr16 = *reinterpret_cast<const uint4*>(g_bufC + off);
                float2 r0 = __half22float2(*reinterpret_cast<__half2*>(&rr16.x));
                float2 r1 = __half22float2(*reinterpret_cast<__half2*>(&rr16.y));
                float2 r2 = __half22float2(*reinterpret_cast<__half2*>(&rr16.z));
                float2 r3 = __half22float2(*reinterpret_cast<__half2*>(&rr16.w));
                float4 o0, o1;
                o0.x = y[0] + r0.x; o0.y = y[1] + r0.y;
                o0.z = y[2] + r1.x; o0.w = y[3] + r1.y;
                o1.x = y[4] + r2.x; o1.y = y[5] + r2.y;
                o1.z = y[6] + r3.x; o1.w = y[7] + r3.y;
                __stcs(reinterpret_cast<float4*>(dout + off), o0);
                __stcs(reinterpret_cast<float4*>(dout + off + 4), o1);
            }
        }
        #pragma unroll
        for (int j = 0; j < 8; j++) {
            accM[j] = __dp4a((int)win[j], wr1, accT[j]);
            accT[j] = __dp4a((int)win[j], wr0, 0);
        }
    }

    if (WHICH == 0) {
        #pragma unroll
        for (int off = 16; off; off >>= 1) lmax = fmaxf(lmax, __shfl_xor_sync(0xFFFFFFFFu, lmax, off));
        __shared__ float wm[4];
        if (lane == 0) wm[warp] = lmax;
        __syncthreads();
        if (threadIdx.x == 0)
            atomicMax(&g_amax[2], __float_as_uint(fmaxf(fmaxf(wm[0], wm[1]), fmaxf(wm[2], wm[3]))));
    }
}

// ---------------- launch ------------------------------------------------------
extern "C" void kernel_launch(void* const* d_in, const int* in_sizes, int n_in,
                              void* d_out, int out_size)
{
    const float* x      = (const float*)d_in[0];
    const float* w_p1   = (const float*)d_in[1];
    const float* w_f1   = (const float*)d_in[2];
    const float* w_p2   = (const float*)d_in[3];
    const float* w_f2   = (const float*)d_in[4];
    const float* alpha1 = (const float*)d_in[5];
    const float* alpha2 = (const float*)d_in[6];
    float* out = (float*)d_out;

    k_init<<<2052, 256>>>((const float4*)x, NTOT / 4, w_p1, w_f1, w_p2, w_f2);

    k_pw0<<<NPIX / 512, 128>>>();                // bufC -> bufA(s16), amax y1
    k_dw<0><<<8192, 128>>>(nullptr, alpha1);     // bufA -> bufB(raw acc s16), amax y3
    k_pw1<<<NPIX / 512, 128>>>(alpha1);          // bufB -> bufA(s16), amax y4
    k_dw<1><<<8192, 128>>>(out, alpha2);         // bufA -> out (+x16)
}

// round 7
// speedup vs baseline: 1.0323x; 1.0323x over previous
#include <cuda_runtime.h>
#include <cuda_fp16.h>
#include <cstdint>

#define HW    65536
#define CCH   64
#define NPIX  (16 * HW)            // 1,048,576 pixels
#define NTOT  (16 * CCH * HW)      // 67,108,864 elements

// ---------------- device scratch (allocation-free) ---------------------------
__device__ __half   g_bufA[NTOT];
__device__ __half   g_bufB[NTOT];
__device__ __half   g_bufC[NTOT];     // fp16 shadow of x
__device__ unsigned g_amax[4];        // abs-max bits of: x, y1, y3, y4 (idempotent)
__device__ float    g_wscale[4];      // scales of: w_p1, w_f1, w_p2, w_f2
__device__ int      g_qwp[2][1024];   // packed int8 pointwise weights [co][ci/4]
__device__ int      g_qwfi[2][192];   // packed int8 dw weight rows [c][3] = (w0,w1,w2,0)

// ---------------- init: weight prep (blocks 0-3) + absmax/x16 (rest) ---------
__global__ void __launch_bounds__(256) k_init(const float4* __restrict__ x, int nvec,
                                              const float* __restrict__ wp1,
                                              const float* __restrict__ wf1,
                                              const float* __restrict__ wp2,
                                              const float* __restrict__ wf2)
{
    if (blockIdx.x < 4) {
        int b = blockIdx.x;   // 0:wp1 1:wf1 2:wp2 3:wf2
        const float* w = (b == 0) ? wp1 : (b == 1) ? wf1 : (b == 2) ? wp2 : wf2;
        int n = (b & 1) ? 576 : 4096;

        __shared__ float red[256];
        float m = 0.f;
        for (int i = threadIdx.x; i < n; i += 256) m = fmaxf(m, fabsf(w[i]));
        red[threadIdx.x] = m;
        __syncthreads();
        for (int s = 128; s > 0; s >>= 1) {
            if (threadIdx.x < s) red[threadIdx.x] = fmaxf(red[threadIdx.x], red[threadIdx.x + s]);
            __syncthreads();
        }
        __shared__ float s_scale;
        if (threadIdx.x == 0) {
            float sc = red[0] / 7.0f + 1e-12f;
            g_wscale[b] = sc;
            s_scale = sc;
        }
        __syncthreads();
        float sc = s_scale;

        if (b & 1) {
            for (int i = threadIdx.x; i < 192; i += 256) {
                const float* wr = w + (i / 3) * 9 + (i % 3) * 3;
                int q0 = (int)fminf(fmaxf(rintf(wr[0] / sc), -7.f), 7.f);
                int q1 = (int)fminf(fmaxf(rintf(wr[1] / sc), -7.f), 7.f);
                int q2 = (int)fminf(fmaxf(rintf(wr[2] / sc), -7.f), 7.f);
                g_qwfi[b >> 1][i] = (q0 & 0xFF) | ((q1 & 0xFF) << 8) | ((q2 & 0xFF) << 16);
            }
        } else {
            for (int i = threadIdx.x; i < 1024; i += 256) {
                int word = 0;
                #pragma unroll
                for (int j = 0; j < 4; j++) {
                    float q = fminf(fmaxf(rintf(w[i * 4 + j] / sc), -7.f), 7.f);
                    word |= ((int)q & 0xFF) << (8 * j);
                }
                g_qwp[b >> 1][i] = word;
            }
        }
        return;
    }

    // ---- absmax(x) + fp16 shadow copy ----
    uint2* __restrict__ c16 = reinterpret_cast<uint2*>(g_bufC);
    int stride = (gridDim.x - 4) * 256;
    float m = 0.f;
    for (int i = (blockIdx.x - 4) * 256 + threadIdx.x; i < nvec; i += stride) {
        float4 v = __ldcs(&x[i]);
        __half2 h01 = __floats2half2_rn(v.x, v.y);
        __half2 h23 = __floats2half2_rn(v.z, v.w);
        uint2 st;
        st.x = *reinterpret_cast<unsigned*>(&h01);
        st.y = *reinterpret_cast<unsigned*>(&h23);
        c16[i] = st;
        m = fmaxf(m, fmaxf(fmaxf(fabsf(v.x), fabsf(v.y)), fmaxf(fabsf(v.z), fabsf(v.w))));
    }
    #pragma unroll
    for (int off = 16; off; off >>= 1) m = fmaxf(m, __shfl_xor_sync(0xFFFFFFFFu, m, off));
    __shared__ float wm[8];
    int lane = threadIdx.x & 31, wid = threadIdx.x >> 5;
    if (lane == 0) wm[wid] = m;
    __syncthreads();
    if (threadIdx.x == 0) {
        float mm = wm[0];
        #pragma unroll
        for (int i = 1; i < 8; i++) mm = fmaxf(mm, wm[i]);
        atomicMax(&g_amax[0], __float_as_uint(mm));
    }
}

// ---------------- pointwise 1x1 conv (dp4a), 4 pixels/thread -----------------
// WHICH 0: in = bufC (half x), out = bufA (half), amax 0 -> 1
// WHICH 1: in = bufB (half),   out = bufA (half), amax 2 -> 3
template<int WHICH>
__global__ void __launch_bounds__(128) k_pw()
{
    __shared__ __align__(16) int ws[1024];
    for (int i = threadIdx.x; i < 1024; i += 128) ws[i] = g_qwp[WHICH][i];
    __syncthreads();

    float in_max = __uint_as_float(g_amax[WHICH * 2]);
    float s_in = in_max * (1.0f / 127.0f) + 1e-12f;
    float inv  = 1.0f / s_in;
    float osc  = s_in * g_wscale[WHICH * 2];

    unsigned p  = (blockIdx.x * 128u + threadIdx.x) * 4u;   // first of 4 pixels
    unsigned base = (p >> 16) * (CCH * HW) + (p & 0xFFFFu);
    const __half* in = (WHICH == 0) ? g_bufC : g_bufB;

    int xq0[16], xq1[16], xq2[16], xq3[16];
    #pragma unroll
    for (int k = 0; k < 16; k++) {
        int w0 = 0, w1 = 0, w2 = 0, w3 = 0;
        #pragma unroll
        for (int j = 0; j < 4; j++) {
            uint2 raw = *reinterpret_cast<const uint2*>(in + base + (unsigned)(4 * k + j) * HW);
            float2 f01 = __half22float2(*reinterpret_cast<__half2*>(&raw.x));
            float2 f23 = __half22float2(*reinterpret_cast<__half2*>(&raw.y));
            w0 |= (__float2int_rn(f01.x * inv) & 0xFF) << (8 * j);
            w1 |= (__float2int_rn(f01.y * inv) & 0xFF) << (8 * j);
            w2 |= (__float2int_rn(f23.x * inv) & 0xFF) << (8 * j);
            w3 |= (__float2int_rn(f23.y * inv) & 0xFF) << (8 * j);
        }
        xq0[k] = w0; xq1[k] = w1; xq2[k] = w2; xq3[k] = w3;
    }

    float lmax = 0.f;
    #pragma unroll 2
    for (int co = 0; co < 64; co++) {
        int a0 = 0, a1 = 0, a2 = 0, a3 = 0;
        #pragma unroll
        for (int k4 = 0; k4 < 4; k4++) {
            int4 w4 = *reinterpret_cast<const int4*>(&ws[co * 16 + k4 * 4]);
            a0 = __dp4a(w4.x, xq0[4 * k4 + 0], a0);
            a0 = __dp4a(w4.y, xq0[4 * k4 + 1], a0);
            a0 = __dp4a(w4.z, xq0[4 * k4 + 2], a0);
            a0 = __dp4a(w4.w, xq0[4 * k4 + 3], a0);
            a1 = __dp4a(w4.x, xq1[4 * k4 + 0], a1);
            a1 = __dp4a(w4.y, xq1[4 * k4 + 1], a1);
            a1 = __dp4a(w4.z, xq1[4 * k4 + 2], a1);
            a1 = __dp4a(w4.w, xq1[4 * k4 + 3], a1);
            a2 = __dp4a(w4.x, xq2[4 * k4 + 0], a2);
            a2 = __dp4a(w4.y, xq2[4 * k4 + 1], a2);
            a2 = __dp4a(w4.z, xq2[4 * k4 + 2], a2);
            a2 = __dp4a(w4.w, xq2[4 * k4 + 3], a2);
            a3 = __dp4a(w4.x, xq3[4 * k4 + 0], a3);
            a3 = __dp4a(w4.y, xq3[4 * k4 + 1], a3);
            a3 = __dp4a(w4.z, xq3[4 * k4 + 2], a3);
            a3 = __dp4a(w4.w, xq3[4 * k4 + 3], a3);
        }
        float y0 = (float)a0 * osc;
        float y1 = (float)a1 * osc;
        float y2 = (float)a2 * osc;
        float y3 = (float)a3 * osc;
        lmax = fmaxf(lmax, fmaxf(fmaxf(fabsf(y0), fabsf(y1)), fmaxf(fabsf(y2), fabsf(y3))));
        __half2 h01 = __floats2half2_rn(y0, y1);
        __half2 h23 = __floats2half2_rn(y2, y3);
        uint2 st;
        st.x = *reinterpret_cast<unsigned*>(&h01);
        st.y = *reinterpret_cast<unsigned*>(&h23);
        *reinterpret_cast<uint2*>(g_bufA + base + (unsigned)co * HW) = st;
    }

    #pragma unroll
    for (int off = 16; off; off >>= 1) lmax = fmaxf(lmax, __shfl_xor_sync(0xFFFFFFFFu, lmax, off));
    __shared__ float wm[4];
    int lane = threadIdx.x & 31, wid = threadIdx.x >> 5;
    if (lane == 0) wm[wid] = lmax;
    __syncthreads();
    if (threadIdx.x == 0)
        atomicMax(&g_amax[WHICH * 2 + 1],
                  __float_as_uint(fmaxf(fmaxf(wm[0], wm[1]), fmaxf(wm[2], wm[3]))));
}

// ---------------- depthwise 3x3 (exact int8 dp4a) + PReLU (+residual) --------
// WHICH 0: bufA(half) -> bufB(half), amax_in [1], fused amax_out [2]
// WHICH 1: bufA(half) -> dout(fp32) + residual bufC(half x), amax_in [3]
// Block: 128 thr = 4 warps; each warp: 16 output rows x 256 cols (8 cols/lane).
// Grid: 1024 (b*c) x 4 strips of 64 rows.
template<int WHICH>
__global__ void __launch_bounds__(128) k_dw(float* __restrict__ dout,
                                            const float* __restrict__ alpha)
{
    int bc    = blockIdx.x >> 2;     // 0..1023
    int strip = blockIdx.x & 3;
    int c     = bc & 63;
    int warp  = threadIdx.x >> 5;
    int lane  = threadIdx.x & 31;
    int rbase = strip * 64 + warp * 16;
    int col0  = lane * 8;

    float in_max = __uint_as_float(g_amax[WHICH == 0 ? 1 : 3]);
    float s_in = in_max * (1.0f / 127.0f) + 1e-12f;
    float inv  = 1.0f / s_in;
    float osc  = s_in * g_wscale[WHICH == 0 ? 1 : 3];   // int acc -> fp value

    int wr0 = g_qwfi[WHICH][c * 3 + 0];
    int wr1 = g_qwfi[WHICH][c * 3 + 1];
    int wr2 = g_qwfi[WHICH][c * 3 + 2];
    float a = alpha[c];

    const __half* in = g_bufA + (unsigned)bc * HW;
    int accT[8], accM[8];
    #pragma unroll
    for (int j = 0; j < 8; j++) { accT[j] = 0; accM[j] = 0; }
    float lmax = 0.f;

    uint4 nxt;
    {
        int rr = rbase - 1;
        nxt = (rr >= 0) ? *reinterpret_cast<const uint4*>(in + rr * 256 + col0)
                        : make_uint4(0, 0, 0, 0);
    }

    #pragma unroll 3
    for (int k = 0; k < 18; k++) {
        uint4 raw = nxt;
        int rr = rbase - 1 + k;
        bool valid = (rr >= 0 && rr < 256);
        if (k < 17) {                      // prefetch next row
            int rn = rbase + k;
            nxt = (rn < 256) ? *reinterpret_cast<const uint4*>(in + rn * 256 + col0)
                             : make_uint4(0, 0, 0, 0);
        }

        unsigned wA = 0, wB = 0;
        if (valid) {
            float2 f0 = __half22float2(*reinterpret_cast<__half2*>(&raw.x));
            float2 f1 = __half22float2(*reinterpret_cast<__half2*>(&raw.y));
            float2 f2 = __half22float2(*reinterpret_cast<__half2*>(&raw.z));
            float2 f3 = __half22float2(*reinterpret_cast<__half2*>(&raw.w));
            int q0 = __float2int_rn(f0.x * inv), q1 = __float2int_rn(f0.y * inv);
            int q2 = __float2int_rn(f1.x * inv), q3 = __float2int_rn(f1.y * inv);
            int q4 = __float2int_rn(f2.x * inv), q5 = __float2int_rn(f2.y * inv);
            int q6 = __float2int_rn(f3.x * inv), q7 = __float2int_rn(f3.y * inv);
            wA = __byte_perm(__byte_perm(q0, q1, 0x0040),
                             __byte_perm(q2, q3, 0x0040), 0x5410);
            wB = __byte_perm(__byte_perm(q4, q5, 0x0040),
                             __byte_perm(q6, q7, 0x0040), 0x5410);
        }
        unsigned wPrev = __shfl_up_sync(0xFFFFFFFFu, wB, 1);
        unsigned wNext = __shfl_down_sync(0xFFFFFFFFu, wA, 1);
        if (lane == 0)  wPrev = 0;    // image left edge
        if (lane == 31) wNext = 0;    // image right edge

        // 8 sliding windows: bytes (q[j-1], q[j], q[j+1], X) — X hits weight 0
        unsigned win[8];
        win[0] = __byte_perm(wPrev, wA, 0x0543);
        win[1] = wA;
        win[2] = __byte_perm(wA, wB, 0x4321);
        win[3] = __byte_perm(wA, wB, 0x5432);
        win[4] = __byte_perm(wA, wB, 0x6543);
        win[5] = wB;
        win[6] = __byte_perm(wB, wNext, 0x4321);
        win[7] = __byte_perm(wB, wNext, 0x5432);

        if (k >= 2) {
            int ro = rbase + k - 2;
            unsigned off = (unsigned)bc * HW + (unsigned)(ro * 256 + col0);
            float y[8];
            #pragma unroll
            for (int j = 0; j < 8; j++) {
                int acc = __dp4a((int)win[j], wr2, accM[j]);
                float v = (float)acc * osc;
                y[j] = (v > 0.f) ? v : a * v;
            }
            if (WHICH == 0) {
                #pragma unroll
                for (int j = 0; j < 8; j++) lmax = fmaxf(lmax, fabsf(y[j]));
                uint4 st;
                __half2 h0 = __floats2half2_rn(y[0], y[1]);
                __half2 h1 = __floats2half2_rn(y[2], y[3]);
                __half2 h2 = __floats2half2_rn(y[4], y[5]);
                __half2 h3 = __floats2half2_rn(y[6], y[7]);
                st.x = *reinterpret_cast<unsigned*>(&h0);
                st.y = *reinterpret_cast<unsigned*>(&h1);
                st.z = *reinterpret_cast<unsigned*>(&h2);
                st.w = *reinterpret_cast<unsigned*>(&h3);
                *reinterpret_cast<uint4*>(g_bufB + off) = st;
            } else {
                uint4 rr16 = *reinterpret_cast<const uint4*>(g_bufC + off);
                float2 r0 = __half22float2(*reinterpret_cast<__half2*>(&rr16.x));
                float2 r1 = __half22float2(*reinterpret_cast<__half2*>(&rr16.y));
                float2 r2 = __half22float2(*reinterpret_cast<__half2*>(&rr16.z));
                float2 r3 = __half22float2(*reinterpret_cast<__half2*>(&rr16.w));
                float4 o0, o1;
                o0.x = y[0] + r0.x; o0.y = y[1] + r0.y;
                o0.z = y[2] + r1.x; o0.w = y[3] + r1.y;
                o1.x = y[4] + r2.x; o1.y = y[5] + r2.y;
                o1.z = y[6] + r3.x; o1.w = y[7] + r3.y;
                __stcs(reinterpret_cast<float4*>(dout + off), o0);
                __stcs(reinterpret_cast<float4*>(dout + off + 4), o1);
            }
        }
        #pragma unroll
        for (int j = 0; j < 8; j++) {
            accM[j] = __dp4a((int)win[j], wr1, accT[j]);
            accT[j] = __dp4a((int)win[j], wr0, 0);
        }
    }

    if (WHICH == 0) {
        #pragma unroll
        for (int off = 16; off; off >>= 1) lmax = fmaxf(lmax, __shfl_xor_sync(0xFFFFFFFFu, lmax, off));
        __shared__ float wm[4];
        if (lane == 0) wm[warp] = lmax;
        __syncthreads();
        if (threadIdx.x == 0)
            atomicMax(&g_amax[2],
                      __float_as_uint(fmaxf(fmaxf(wm[0], wm[1]), fmaxf(wm[2], wm[3]))));
    }
}

// ---------------- launch ------------------------------------------------------
extern "C" void kernel_launch(void* const* d_in, const int* in_sizes, int n_in,
                              void* d_out, int out_size)
{
    const float* x      = (const float*)d_in[0];
    const float* w_p1   = (const float*)d_in[1];
    const float* w_f1   = (const float*)d_in[2];
    const float* w_p2   = (const float*)d_in[3];
    const float* w_f2   = (const float*)d_in[4];
    const float* alpha1 = (const float*)d_in[5];
    const float* alpha2 = (const float*)d_in[6];
    float* out = (float*)d_out;

    k_init<<<2052, 256>>>((const float4*)x, NTOT / 4, w_p1, w_f1, w_p2, w_f2);

    k_pw<0><<<NPIX / 512, 128>>>();              // bufC -> bufA, amax y1
    k_dw<0><<<4096, 128>>>(nullptr, alpha1);     // bufA -> bufB, amax y3
    k_pw<1><<<NPIX / 512, 128>>>();              // bufB -> bufA, amax y4
    k_dw<1><<<4096, 128>>>(out, alpha2);         // bufA -> out (+x16)
}